// round 12
// baseline (speedup 1.0000x reference)
#include <cuda_runtime.h>
#include <math.h>
#include <float.h>

#define B_   32
#define T_   50
#define D_   100
#define NQ_  20000
#define NS_  500
#define NU_  10000
#define NBR_ 6
#define SPQ_ 4
#define BT_  (B_*(T_-1))
#define NEG_ (-1.0e9f)

// ---------------- static device scratch ----------------
__device__ float d_PQ2a[NQ_*D_];
__device__ float d_PS2 [NS_*D_];
__device__ float d_PU2 [NU_*D_];
__device__ float d_PQ2b[NQ_*D_];
__device__ float d_Y2 [2*BT_*36*D_];
__device__ float d_X1 [2*BT_*6*D_];
__device__ float d_Y1 [2*BT_*6*D_];
__device__ float d_X1b[2*BT_*6*D_];
__device__ float d_Y1b[2*BT_*6*D_];
__device__ float d_X0 [2*BT_*D_];
__device__ float d_Y0 [2*BT_*D_];
__device__ float d_X0b[2*BT_*D_];
__device__ float d_Y0b[2*BT_*D_];
__device__ float d_X0c[2*BT_*D_];
__device__ float d_Y0c[2*BT_*D_];
__device__ float d_E  [2*BT_*D_];
__device__ float d_Xf [BT_*2*D_];
__device__ float d_et [BT_*D_];
__device__ float d_gip[BT_*4*D_];
__device__ float d_qsc[BT_*5*D_];
__device__ float d_qlog[BT_*5];
__device__ int   d_topk[BT_*10];
__device__ int   d_sval[BT_*11];
__device__ float d_vec[256];      // [0:100) qvec, [100:200) kvec, [200] cq, [201] ck
__device__ float d_bsum[4*D_];

__device__ __forceinline__ float sigf(float x){ return 1.f/(1.f+expf(-x)); }

// ---------------- generic GEMM: C = act(A[MxK] @ W[NxK]^T + bias) ----------------
__global__ void gemm_k(const float* __restrict__ A, const float* __restrict__ W,
                       const float* __restrict__ bias, float* __restrict__ C,
                       int M, int N, int K, int act)
{
    __shared__ float As[16][65];
    __shared__ float Bs[16][65];
    const int bm = blockIdx.y * 64, bn = blockIdx.x * 64;
    const int tid = threadIdx.x;
    const int tr = tid >> 4, tc = tid & 15;
    float acc[4][4] = {};
    for (int k0 = 0; k0 < K; k0 += 16) {
        for (int i = tid; i < 1024; i += 256) {
            int m = i >> 4, k = i & 15;
            int gm = bm + m, gk = k0 + k;
            As[k][m] = (gm < M && gk < K) ? A[(size_t)gm * K + gk] : 0.f;
        }
        for (int i = tid; i < 1024; i += 256) {
            int nn = i >> 4, k = i & 15;
            int gn = bn + nn, gk = k0 + k;
            Bs[k][nn] = (gn < N && gk < K) ? W[(size_t)gn * K + gk] : 0.f;
        }
        __syncthreads();
        #pragma unroll
        for (int k = 0; k < 16; k++) {
            float a[4], b[4];
            #pragma unroll
            for (int i = 0; i < 4; i++) a[i] = As[k][tr*4+i];
            #pragma unroll
            for (int j = 0; j < 4; j++) b[j] = Bs[k][tc*4+j];
            #pragma unroll
            for (int i = 0; i < 4; i++)
                #pragma unroll
                for (int j = 0; j < 4; j++) acc[i][j] = fmaf(a[i], b[j], acc[i][j]);
        }
        __syncthreads();
    }
    #pragma unroll
    for (int i = 0; i < 4; i++) {
        int gm = bm + tr*4 + i;
        if (gm >= M) continue;
        #pragma unroll
        for (int j = 0; j < 4; j++) {
            int gn = bn + tc*4 + j;
            if (gn >= N) continue;
            float v = acc[i][j] + (bias ? bias[gn] : 0.f);
            if (act == 1) v = tanhf(v);
            else if (act == 2) v = fmaxf(v, 0.f);
            C[(size_t)gm * N + gn] = v;
        }
    }
}

// ---------------- attention vectors + combined LSTM bias ----------------
__global__ void k_vec(const float* __restrict__ Wq, const float* __restrict__ bq,
                      const float* __restrict__ Wk, const float* __restrict__ bk,
                      const float* __restrict__ Ww,
                      const float* __restrict__ bih, const float* __restrict__ bhh)
{
    int tid = threadIdx.x;
    if (tid < D_) {
        float s = 0.f;
        for (int j = 0; j < D_; j++) s = fmaf(Ww[j], Wq[j*D_+tid], s);
        d_vec[tid] = s;
    } else if (tid < 2*D_) {
        int d = tid - D_;
        float s = 0.f;
        for (int j = 0; j < D_; j++) s = fmaf(Ww[D_+j], Wk[j*D_+d], s);
        d_vec[D_+d] = s;
    } else if (tid == 2*D_) {
        float s = 0.f; for (int j = 0; j < D_; j++) s = fmaf(bq[j], Ww[j], s);
        d_vec[200] = s;
    } else if (tid == 2*D_+1) {
        float s = 0.f; for (int j = 0; j < D_; j++) s = fmaf(bk[j], Ww[D_+j], s);
        d_vec[201] = s;
    }
    if (tid < 4*D_) d_bsum[tid] = bih[tid] + bhh[tid];
}

// ---------------- i=0,j=2 via projected tables: tanh(mean P3[l3] + P2[l2] + b2) ----------------
__global__ void k_y2(const int* __restrict__ question, const int* __restrict__ user,
                     const int* __restrict__ qnb, const int* __restrict__ snb,
                     const int* __restrict__ unb, const int* __restrict__ q2nb,
                     const float* __restrict__ aggb)
{
    int warp = (blockIdx.x*blockDim.x + threadIdx.x) >> 5;
    int lane = threadIdx.x & 31;
    if (warp >= 2*BT_*36) return;
    int j   = warp % 36;
    int nn  = warp / 36;
    int n   = nn % BT_;
    int tau = nn / BT_;
    int b = n / (T_-1), t = n % (T_-1);
    int i1 = j / 6, j2 = j % 6;
    const float* P3 = (tau == 0) ? d_PS2  : d_PQ2b;
    const float* P2 = (tau == 0) ? d_PQ2a : d_PU2;
    int n2 = 0;
    if (lane == 0) {
        int root = (tau == 0) ? question[b*T_+t] : user[b*T_+t];
        int n1   = (tau == 0) ? qnb[root*NBR_+i1] : unb[root*NBR_+i1];
        n2       = (tau == 0) ? snb[n1*NBR_+j2]   : q2nb[n1*NBR_+j2];
    }
    n2 = __shfl_sync(0xffffffffu, n2, 0);
    int n3l = 0;
    if (lane < NBR_) n3l = (tau == 0) ? qnb[n2*NBR_+lane] : unb[n2*NBR_+lane];
    int n3[NBR_];
    #pragma unroll
    for (int k = 0; k < NBR_; k++) n3[k] = __shfl_sync(0xffffffffu, n3l, k);
    const float* b2 = aggb + 2*D_;
    for (int d = lane; d < D_; d += 32) {
        float s = 0.f;
        #pragma unroll
        for (int k = 0; k < NBR_; k++) s += P3[(size_t)n3[k]*D_+d];
        d_Y2[(size_t)warp*D_+d] = tanhf(s*(1.f/6.f) + P2[(size_t)n2*D_+d] + b2[d]);
    }
}

// ---------------- i=0,j=1 input: mean raw T2[l2] + raw T1[n1] ----------------
__global__ void k_x1(const int* __restrict__ question, const int* __restrict__ user,
                     const int* __restrict__ qnb, const int* __restrict__ snb,
                     const int* __restrict__ unb, const int* __restrict__ q2nb,
                     const float* __restrict__ embQ, const float* __restrict__ embS,
                     const float* __restrict__ embU, const float* __restrict__ embQ2)
{
    int warp = (blockIdx.x*blockDim.x + threadIdx.x) >> 5;
    int lane = threadIdx.x & 31;
    if (warp >= 2*BT_*6) return;
    int i1  = warp % 6;
    int nn  = warp / 6;
    int n   = nn % BT_;
    int tau = nn / BT_;
    int b = n / (T_-1), t = n % (T_-1);
    int n1 = 0;
    if (lane == 0) {
        int root = (tau == 0) ? question[b*T_+t] : user[b*T_+t];
        n1 = (tau == 0) ? qnb[root*NBR_+i1] : unb[root*NBR_+i1];
    }
    n1 = __shfl_sync(0xffffffffu, n1, 0);
    int l2l = 0;
    if (lane < NBR_) l2l = (tau == 0) ? snb[n1*NBR_+lane] : q2nb[n1*NBR_+lane];
    int l2[NBR_];
    #pragma unroll
    for (int k = 0; k < NBR_; k++) l2[k] = __shfl_sync(0xffffffffu, l2l, k);
    const float* T2 = (tau == 0) ? embQ : embU;
    const float* T1 = (tau == 0) ? embS : embQ2;
    for (int d = lane; d < D_; d += 32) {
        float s = 0.f;
        #pragma unroll
        for (int k = 0; k < NBR_; k++) s += T2[(size_t)l2[k]*D_+d];
        d_X1[(size_t)warp*D_+d] = s*(1.f/6.f) + T1[(size_t)n1*D_+d];
    }
}

// ---------------- i=0,j=0 input: mean raw T1[l1] + raw T0[root] ----------------
__global__ void k_x0(const int* __restrict__ question, const int* __restrict__ user,
                     const int* __restrict__ qnb, const int* __restrict__ unb,
                     const float* __restrict__ embQ, const float* __restrict__ embS,
                     const float* __restrict__ embU, const float* __restrict__ embQ2)
{
    int warp = (blockIdx.x*blockDim.x + threadIdx.x) >> 5;
    int lane = threadIdx.x & 31;
    if (warp >= 2*BT_) return;
    int n   = warp % BT_;
    int tau = warp / BT_;
    int b = n / (T_-1), t = n % (T_-1);
    int root = (tau == 0) ? question[b*T_+t] : user[b*T_+t];
    int l1l = 0;
    if (lane < NBR_) l1l = (tau == 0) ? qnb[root*NBR_+lane] : unb[root*NBR_+lane];
    int l1[NBR_];
    #pragma unroll
    for (int k = 0; k < NBR_; k++) l1[k] = __shfl_sync(0xffffffffu, l1l, k);
    const float* T1 = (tau == 0) ? embS : embQ2;
    const float* T0 = (tau == 0) ? embQ : embU;
    for (int d = lane; d < D_; d += 32) {
        float s = 0.f;
        #pragma unroll
        for (int k = 0; k < NBR_; k++) s += T1[(size_t)l1[k]*D_+d];
        d_X0[(size_t)warp*D_+d] = s*(1.f/6.f) + T0[(size_t)root*D_+d];
    }
}

// ---------------- out[r] = mean_k big[r*6+k] + small[r] ----------------
__global__ void k_meanadd(const float* __restrict__ big, const float* __restrict__ small,
                          float* __restrict__ outp, int rows)
{
    int warp = (blockIdx.x*blockDim.x + threadIdx.x) >> 5;
    int lane = threadIdx.x & 31;
    if (warp >= rows) return;
    for (int d = lane; d < D_; d += 32) {
        float s = 0.f;
        #pragma unroll
        for (int k = 0; k < 6; k++) s += big[(size_t)(warp*6+k)*D_+d];
        outp[(size_t)warp*D_+d] = s*(1.f/6.f) + small[(size_t)warp*D_+d];
    }
}

// ---------------- fusion input: [w1*e1 + w2*e2, emb_response[r]] with mask fallback ----------------
__global__ void k_fuse(const int* __restrict__ question, const int* __restrict__ response,
                       const int* __restrict__ mask,
                       const float* __restrict__ embQ, const float* __restrict__ embQ2,
                       const float* __restrict__ embR,
                       const float* __restrict__ w1q, const float* __restrict__ w2q)
{
    int i = blockIdx.x*blockDim.x + threadIdx.x;
    if (i >= BT_*D_) return;
    int n = i / D_, d = i % D_;
    int b = n / (T_-1), t = n % (T_-1);
    int m = mask[b*T_+t];
    int q = question[b*T_+t];
    int r = response[b*T_+t];
    float e1 = m ? d_E[(size_t)n*D_+d]       : embQ [(size_t)q*D_+d];
    float e2 = m ? d_E[(size_t)(BT_+n)*D_+d] : embQ2[(size_t)q*D_+d];
    d_Xf[(size_t)n*2*D_+d]    = w1q[0]*e1 + w2q[0]*e2;
    d_Xf[(size_t)n*2*D_+D_+d] = embR[(size_t)r*D_+d];
}

// ---------------- qs_concat rows + query logits ----------------
__global__ void k_qs(const int* __restrict__ question, const int* __restrict__ qsidx,
                     const float* __restrict__ embQ, const float* __restrict__ embS,
                     const float* __restrict__ bw)
{
    int n = blockIdx.x;
    int q = threadIdx.x >> 5, lane = threadIdx.x & 31;
    if (q >= 5) return;
    int b = n / (T_-1), t = n % (T_-1);
    int qn = question[b*T_ + t + 1];
    const float* src = (q == 0) ? (embQ + (size_t)qn*D_)
                                : (embS + (size_t)qsidx[qn*SPQ_ + q - 1]*D_);
    float dot = 0.f;
    for (int d = lane; d < D_; d += 32) {
        float v = src[d];
        d_qsc[(size_t)(n*5+q)*D_+d] = v;
        dot = fmaf(v, d_vec[d], dot);
    }
    #pragma unroll
    for (int off = 16; off; off >>= 1) dot += __shfl_xor_sync(0xffffffffu, dot, off);
    if (lane == 0) d_qlog[n*5+q] = dot + d_vec[200] + bw[0];
}

// ---------------- scores + top-10 (mask-before-select, ties -> lowest index) ----------------
__global__ void k_topk(const int* __restrict__ question, const float* __restrict__ embQ)
{
    __shared__ float qn_s[D_];
    __shared__ float sc[T_];
    int n = blockIdx.x, tid = threadIdx.x;
    int b = n / (T_-1), t = n % (T_-1);
    int qn = question[b*T_ + t + 1];
    for (int d = tid; d < D_; d += 64) qn_s[d] = embQ[(size_t)qn*D_+d];
    __syncthreads();
    if (tid < T_) {
        float s = NEG_;
        if (tid < t) {
            const float* row = embQ + (size_t)question[b*T_+tid]*D_;
            float a0 = 0.f, a1 = 0.f;
            for (int d = 0; d < D_; d += 2) {
                a0 = fmaf(row[d],   qn_s[d],   a0);
                a1 = fmaf(row[d+1], qn_s[d+1], a1);
            }
            s = a0 + a1;
        }
        sc[tid] = s;
    }
    __syncthreads();
    if (tid < 32) {
        float v0 = sc[tid];                               int i0  = tid;
        float v1 = (tid+32 < T_) ? sc[tid+32] : -FLT_MAX; int i1t = tid + 32;
        for (int r = 0; r < 10; r++) {
            float bv; int bi;
            if (v0 > v1 || (v0 == v1 && i0 < i1t)) { bv = v0; bi = i0; } else { bv = v1; bi = i1t; }
            #pragma unroll
            for (int off = 16; off; off >>= 1) {
                float ov = __shfl_xor_sync(0xffffffffu, bv, off);
                int   oi = __shfl_xor_sync(0xffffffffu, bi, off);
                if (ov > bv || (ov == bv && oi < bi)) { bv = ov; bi = oi; }
            }
            if (tid == 0) {
                d_topk[n*10+r]   = bi;
                d_sval[n*11+1+r] = (bi < t) ? 1 : 0;
            }
            if (i0  == bi) v0 = -FLT_MAX;
            if (i1t == bi) v1 = -FLT_MAX;
        }
        if (tid == 0) d_sval[n*11] = 1;
    }
}

// ---------------- sequential LSTM + attention readout: one CTA per batch row ----------------
__global__ void __launch_bounds__(416,1) k_seq(const int* __restrict__ mask,
                                               const float* __restrict__ Whh,
                                               float* __restrict__ out)
{
    __shared__ float sh[T_][D_];
    __shared__ float kh[T_];
    __shared__ float h[D_], c[D_], g[4*D_];
    __shared__ float gm[55], lg[55];
    int b = blockIdx.x, tid = threadIdx.x;
    int lane = tid & 31, warp = tid >> 5;   // 13 warps
    for (int i = tid; i < T_*D_; i += 416) (&sh[0][0])[i] = 0.f;
    for (int i = tid; i < D_; i += 416) { h[i] = 0.f; c[i] = 0.f; }
    if (tid < T_) kh[tid] = 0.f;
    if (tid == 0) out[b*T_] = 0.5f;
    float w[D_];
    if (tid < 4*D_) {
        #pragma unroll
        for (int j = 0; j < D_; j++) w[j] = Whh[(size_t)tid*D_+j];
    }
    __syncthreads();
    for (int t = 0; t < T_-1; t++) {
        int n = b*(T_-1)+t;
        if (tid < 4*D_) {
            float s = d_gip[(size_t)n*4*D_+tid];
            #pragma unroll
            for (int j = 0; j < D_; j++) s = fmaf(w[j], h[j], s);
            g[tid] = s;
        }
        __syncthreads();
        int m = mask[b*T_+t];
        if (tid < D_) {
            float gi = g[tid], gf = g[D_+tid], gg = g[2*D_+tid], go = g[3*D_+tid];
            float c2 = sigf(gf)*c[tid] + sigf(gi)*tanhf(gg);
            float h2 = sigf(go)*tanhf(c2);
            float hn = m ? h2 : h[tid];
            float cn = m ? c2 : c[tid];
            h[tid] = hn; c[tid] = cn; sh[t][tid] = hn;
        }
        __syncthreads();
        if (warp == 0) {
            float s = 0.f;
            for (int d = lane; d < D_; d += 32) s = fmaf(d_vec[D_+d], h[d], s);
            #pragma unroll
            for (int o = 16; o; o >>= 1) s += __shfl_xor_sync(0xffffffffu, s, o);
            if (lane == 0) kh[t] = s;
        }
        __syncthreads();
        for (int p = warp; p < 55; p += 13) {
            int q = p / 11, sidx = p % 11;
            const float* qr = d_qsc + (size_t)(n*5+q)*D_;
            const float* st;
            float kl; int valid;
            if (sidx == 0) { st = h; kl = kh[t]; valid = 1; }
            else {
                int ii = d_topk[n*10 + sidx - 1];
                st = sh[ii]; kl = kh[ii]; valid = d_sval[n*11 + sidx];
            }
            float s = 0.f;
            for (int d = lane; d < D_; d += 32) s = fmaf(qr[d], st[d], s);
            #pragma unroll
            for (int o = 16; o; o >>= 1) s += __shfl_xor_sync(0xffffffffu, s, o);
            if (lane == 0) {
                gm[p] = s;
                lg[p] = valid ? (d_qlog[n*5+q] + kl + d_vec[201]) : NEG_;
            }
        }
        __syncthreads();
        if (warp == 0) {
            float mx = -FLT_MAX;
            for (int p = lane; p < 55; p += 32) mx = fmaxf(mx, lg[p]);
            #pragma unroll
            for (int o = 16; o; o >>= 1) mx = fmaxf(mx, __shfl_xor_sync(0xffffffffu, mx, o));
            float se = 0.f, sg = 0.f;
            for (int p = lane; p < 55; p += 32) {
                float e = expf(lg[p] - mx);
                se += e; sg = fmaf(e, gm[p], sg);
            }
            #pragma unroll
            for (int o = 16; o; o >>= 1) {
                se += __shfl_xor_sync(0xffffffffu, se, o);
                sg += __shfl_xor_sync(0xffffffffu, sg, o);
            }
            if (lane == 0) out[b*T_ + t + 1] = sigf(sg / se);
        }
        __syncthreads();
    }
}

// ---------------- host launcher ----------------
#define SYM(p, s) do { void* v_; cudaGetSymbolAddress(&v_, s); p = (float*)v_; } while (0)

extern "C" void kernel_launch(void* const* d_in, const int* in_sizes, int n_in,
                              void* d_out, int out_size)
{
    const int *user=(const int*)d_in[0], *question=(const int*)d_in[1];
    const int *response=(const int*)d_in[2], *mask=(const int*)d_in[3];
    const int *qnb=(const int*)d_in[4], *snb=(const int*)d_in[5];
    const int *unb=(const int*)d_in[6], *q2nb=(const int*)d_in[7], *qsidx=(const int*)d_in[8];
    const float *embQ=(const float*)d_in[9], *embQ2=(const float*)d_in[10];
    const float *embS=(const float*)d_in[11], *embU=(const float*)d_in[12], *embR=(const float*)d_in[13];
    const float *w1q=(const float*)d_in[14], *w2q=(const float*)d_in[15];
    const float *Wih=(const float*)d_in[16], *Whh=(const float*)d_in[17];
    const float *bih=(const float*)d_in[18], *bhh=(const float*)d_in[19];
    const float *aggw=(const float*)d_in[20], *aggb=(const float*)d_in[21];
    const float *Wal=(const float*)d_in[22], *bal=(const float*)d_in[23];
    const float *Wq=(const float*)d_in[24], *bq=(const float*)d_in[25];
    const float *Wk=(const float*)d_in[26], *bk=(const float*)d_in[27];
    const float *Ww=(const float*)d_in[28], *bw=(const float*)d_in[29];
    const float *Wf=(const float*)d_in[30], *bf=(const float*)d_in[31];
    float* out = (float*)d_out;

    float *PQ2a, *PS2, *PU2, *PQ2b, *Y2, *X1, *Y1, *X1b, *Y1b;
    float *X0, *Y0, *X0b, *Y0b, *X0c, *Y0c, *E, *Xf, *et, *gip, *bsum;
    SYM(PQ2a, d_PQ2a); SYM(PS2, d_PS2); SYM(PU2, d_PU2); SYM(PQ2b, d_PQ2b);
    SYM(Y2, d_Y2); SYM(X1, d_X1); SYM(Y1, d_Y1); SYM(X1b, d_X1b); SYM(Y1b, d_Y1b);
    SYM(X0, d_X0); SYM(Y0, d_Y0); SYM(X0b, d_X0b); SYM(Y0b, d_Y0b);
    SYM(X0c, d_X0c); SYM(Y0c, d_Y0c); SYM(E, d_E); SYM(Xf, d_Xf);
    SYM(et, d_et); SYM(gip, d_gip); SYM(bsum, d_bsum);

    const float* w2 = aggw + 2*D_*D_;
    const float* w1 = aggw + 1*D_*D_;
    const float* w0 = aggw;
    const float* b1 = aggb + 1*D_;
    const float* b0 = aggb;

    k_vec<<<1, 512>>>(Wq, bq, Wk, bk, Ww, bih, bhh);

    dim3 tb(256);
    // w2-projections of the four tables (no bias, no activation)
    gemm_k<<<dim3(2, (NQ_+63)/64), tb>>>(embQ,  w2, nullptr, PQ2a, NQ_, D_, D_, 0);
    gemm_k<<<dim3(2, (NS_+63)/64), tb>>>(embS,  w2, nullptr, PS2,  NS_, D_, D_, 0);
    gemm_k<<<dim3(2, (NU_+63)/64), tb>>>(embU,  w2, nullptr, PU2,  NU_, D_, D_, 0);
    gemm_k<<<dim3(2, (NQ_+63)/64), tb>>>(embQ2, w2, nullptr, PQ2b, NQ_, D_, D_, 0);

    // i=0, j=2 (linearized)
    { int warps = 2*BT_*36; k_y2<<<(warps*32 + 255)/256, 256>>>(question, user, qnb, snb, unb, q2nb, aggb); }
    // i=0, j=1
    { int warps = 2*BT_*6; k_x1<<<(warps*32 + 255)/256, 256>>>(question, user, qnb, snb, unb, q2nb, embQ, embS, embU, embQ2); }
    gemm_k<<<dim3(2, (2*BT_*6+63)/64), tb>>>(X1, w1, b1, Y1, 2*BT_*6, D_, D_, 1);
    // i=0, j=0
    { int warps = 2*BT_; k_x0<<<(warps*32 + 255)/256, 256>>>(question, user, qnb, unb, embQ, embS, embU, embQ2); }
    gemm_k<<<dim3(2, (2*BT_+63)/64), tb>>>(X0, w0, b0, Y0, 2*BT_, D_, D_, 1);
    // i=1, j=1
    { int warps = 2*BT_*6; k_meanadd<<<(warps*32 + 255)/256, 256>>>(Y2, Y1, X1b, warps); }
    gemm_k<<<dim3(2, (2*BT_*6+63)/64), tb>>>(X1b, w1, b1, Y1b, 2*BT_*6, D_, D_, 1);
    // i=1, j=0
    { int warps = 2*BT_; k_meanadd<<<(warps*32 + 255)/256, 256>>>(Y1, Y0, X0b, warps); }
    gemm_k<<<dim3(2, (2*BT_+63)/64), tb>>>(X0b, w0, b0, Y0b, 2*BT_, D_, D_, 1);
    // i=2, j=0
    { int warps = 2*BT_; k_meanadd<<<(warps*32 + 255)/256, 256>>>(Y1b, Y0b, X0c, warps); }
    gemm_k<<<dim3(2, (2*BT_+63)/64), tb>>>(X0c, w0, b0, Y0c, 2*BT_, D_, D_, 1);
    // final aggregate
    gemm_k<<<dim3(2, (2*BT_+63)/64), tb>>>(Y0c, Wal, bal, E, 2*BT_, D_, D_, 1);

    // fusion + gates input
    k_fuse<<<(BT_*D_ + 255)/256, 256>>>(question, response, mask, embQ, embQ2, embR, w1q, w2q);
    gemm_k<<<dim3(2, (BT_+63)/64), tb>>>(Xf, Wf, bf, et, BT_, D_, 2*D_, 2);
    gemm_k<<<dim3(7, (BT_+63)/64), tb>>>(et, Wih, bsum, gip, BT_, 4*D_, D_, 0);

    // attention inputs
    k_qs<<<BT_, 160>>>(question, qsidx, embQ, embS, bw);
    k_topk<<<BT_, 64>>>(question, embQ);

    // sequential recurrence + readout
    k_seq<<<B_, 416>>>(mask, Whh, out);
}

// round 16
// speedup vs baseline: 1.2012x; 1.2012x over previous
#include <cuda_runtime.h>
#include <math.h>
#include <float.h>

#define B_   32
#define T_   50
#define D_   100
#define NQ_  20000
#define NS_  500
#define NU_  10000
#define NBR_ 6
#define SPQ_ 4
#define BT_  (B_*(T_-1))
#define NEG_ (-1.0e9f)

// ---------------- static device scratch ----------------
__device__ float d_X2Q[NS_*NBR_*D_];   // tree0 level-2 inputs, indexed (s,k)
__device__ float d_Y2Q[NS_*NBR_*D_];
__device__ float d_X1S[NS_*D_];        // tree0 level-1 (per skill)
__device__ float d_Y1S[NS_*D_];
__device__ float d_X1Sb[NS_*D_];
__device__ float d_Y1Sb[NS_*D_];
__device__ float d_X2U[NU_*D_];        // tree1 level-2 (per user)
__device__ float d_Y2U[NU_*D_];
__device__ float d_X1Q[BT_*NBR_*D_];   // tree1 level-1 (per root instance x nbr)
__device__ float d_Y1Q[BT_*NBR_*D_];
__device__ float d_X1Qb[BT_*NBR_*D_];
__device__ float d_Y1Qb[BT_*NBR_*D_];
__device__ float d_X0 [2*BT_*D_];
__device__ float d_Y0 [2*BT_*D_];
__device__ float d_X0b[2*BT_*D_];
__device__ float d_Y0b[2*BT_*D_];
__device__ float d_X0c[2*BT_*D_];
__device__ float d_Y0c[2*BT_*D_];
__device__ float d_E  [2*BT_*D_];
__device__ float d_Xf [BT_*2*D_];
__device__ float d_et [BT_*D_];
__device__ float d_gip[BT_*4*D_];
__device__ float d_qsc[BT_*5*D_];
__device__ float d_qlog[BT_*5];
__device__ int   d_topk[BT_*10];
__device__ int   d_sval[BT_*11];
__device__ float d_vec[256];      // [0:100) qvec, [100:200) kvec, [200] cq, [201] ck
__device__ float d_bsum[4*D_];

__device__ __forceinline__ float sigf(float x){ return 1.f/(1.f+expf(-x)); }

// ---------------- generic GEMM: C = act(A[MxK] @ W[NxK]^T + bias) ----------------
__global__ void gemm_k(const float* __restrict__ A, const float* __restrict__ W,
                       const float* __restrict__ bias, float* __restrict__ C,
                       int M, int N, int K, int act)
{
    __shared__ float As[16][65];
    __shared__ float Bs[16][65];
    const int bm = blockIdx.y * 64, bn = blockIdx.x * 64;
    const int tid = threadIdx.x;
    const int tr = tid >> 4, tc = tid & 15;
    float acc[4][4] = {};
    for (int k0 = 0; k0 < K; k0 += 16) {
        for (int i = tid; i < 1024; i += 256) {
            int m = i >> 4, k = i & 15;
            int gm = bm + m, gk = k0 + k;
            As[k][m] = (gm < M && gk < K) ? A[(size_t)gm * K + gk] : 0.f;
        }
        for (int i = tid; i < 1024; i += 256) {
            int nn = i >> 4, k = i & 15;
            int gn = bn + nn, gk = k0 + k;
            Bs[k][nn] = (gn < N && gk < K) ? W[(size_t)gn * K + gk] : 0.f;
        }
        __syncthreads();
        #pragma unroll
        for (int k = 0; k < 16; k++) {
            float a[4], b[4];
            #pragma unroll
            for (int i = 0; i < 4; i++) a[i] = As[k][tr*4+i];
            #pragma unroll
            for (int j = 0; j < 4; j++) b[j] = Bs[k][tc*4+j];
            #pragma unroll
            for (int i = 0; i < 4; i++)
                #pragma unroll
                for (int j = 0; j < 4; j++) acc[i][j] = fmaf(a[i], b[j], acc[i][j]);
        }
        __syncthreads();
    }
    #pragma unroll
    for (int i = 0; i < 4; i++) {
        int gm = bm + tr*4 + i;
        if (gm >= M) continue;
        #pragma unroll
        for (int j = 0; j < 4; j++) {
            int gn = bn + tc*4 + j;
            if (gn >= N) continue;
            float v = acc[i][j] + (bias ? bias[gn] : 0.f);
            if (act == 1) v = tanhf(v);
            else if (act == 2) v = fmaxf(v, 0.f);
            C[(size_t)gm * N + gn] = v;
        }
    }
}

// ---------------- attention vectors + combined LSTM bias ----------------
__global__ void k_vec(const float* __restrict__ Wq, const float* __restrict__ bq,
                      const float* __restrict__ Wk, const float* __restrict__ bk,
                      const float* __restrict__ Ww,
                      const float* __restrict__ bih, const float* __restrict__ bhh)
{
    int tid = threadIdx.x;
    if (tid < D_) {
        float s = 0.f;
        for (int j = 0; j < D_; j++) s = fmaf(Ww[j], Wq[j*D_+tid], s);
        d_vec[tid] = s;
    } else if (tid < 2*D_) {
        int d = tid - D_;
        float s = 0.f;
        for (int j = 0; j < D_; j++) s = fmaf(Ww[D_+j], Wk[j*D_+d], s);
        d_vec[D_+d] = s;
    } else if (tid == 2*D_) {
        float s = 0.f; for (int j = 0; j < D_; j++) s = fmaf(bq[j], Ww[j], s);
        d_vec[200] = s;
    } else if (tid == 2*D_+1) {
        float s = 0.f; for (int j = 0; j < D_; j++) s = fmaf(bk[j], Ww[D_+j], s);
        d_vec[201] = s;
    }
    if (tid < 4*D_) d_bsum[tid] = bih[tid] + bhh[tid];
}

// ================= per-node aggregation gathers =================
// tree0 level-2 slot (s,k): q = snb[s,k]; X = mean_j embS[qnb[q,j]] + embQ[q]
__global__ void k_x2q(const int* __restrict__ snb, const int* __restrict__ qnb,
                      const float* __restrict__ embQ, const float* __restrict__ embS)
{
    int warp = (blockIdx.x*blockDim.x + threadIdx.x) >> 5;
    int lane = threadIdx.x & 31;
    if (warp >= NS_*NBR_) return;
    int q = snb[warp];
    int nl = 0;
    if (lane < NBR_) nl = qnb[q*NBR_+lane];
    int nb[NBR_];
    #pragma unroll
    for (int k = 0; k < NBR_; k++) nb[k] = __shfl_sync(0xffffffffu, nl, k);
    for (int d = lane; d < D_; d += 32) {
        float s = 0.f;
        #pragma unroll
        for (int k = 0; k < NBR_; k++) s += embS[(size_t)nb[k]*D_+d];
        d_X2Q[(size_t)warp*D_+d] = s*(1.f/6.f) + embQ[(size_t)q*D_+d];
    }
}

// tree0 level-1 (per skill s): X = mean_k embQ[snb[s,k]] + embS[s]
__global__ void k_x1s(const int* __restrict__ snb,
                      const float* __restrict__ embQ, const float* __restrict__ embS)
{
    int warp = (blockIdx.x*blockDim.x + threadIdx.x) >> 5;
    int lane = threadIdx.x & 31;
    if (warp >= NS_) return;
    int nl = 0;
    if (lane < NBR_) nl = snb[warp*NBR_+lane];
    int nb[NBR_];
    #pragma unroll
    for (int k = 0; k < NBR_; k++) nb[k] = __shfl_sync(0xffffffffu, nl, k);
    for (int d = lane; d < D_; d += 32) {
        float s = 0.f;
        #pragma unroll
        for (int k = 0; k < NBR_; k++) s += embQ[(size_t)nb[k]*D_+d];
        d_X1S[(size_t)warp*D_+d] = s*(1.f/6.f) + embS[(size_t)warp*D_+d];
    }
}

// tree1 level-2 (per user u): X = mean_k embQ2[unb[u,k]] + embU[u]
__global__ void k_x2u(const int* __restrict__ unb,
                      const float* __restrict__ embQ2, const float* __restrict__ embU)
{
    int warp = (blockIdx.x*blockDim.x + threadIdx.x) >> 5;
    int lane = threadIdx.x & 31;
    if (warp >= NU_) return;
    int nl = 0;
    if (lane < NBR_) nl = unb[warp*NBR_+lane];
    int nb[NBR_];
    #pragma unroll
    for (int k = 0; k < NBR_; k++) nb[k] = __shfl_sync(0xffffffffu, nl, k);
    for (int d = lane; d < D_; d += 32) {
        float s = 0.f;
        #pragma unroll
        for (int k = 0; k < NBR_; k++) s += embQ2[(size_t)nb[k]*D_+d];
        d_X2U[(size_t)warp*D_+d] = s*(1.f/6.f) + embU[(size_t)warp*D_+d];
    }
}

// tree1 level-1 instance (n,i1): q = unb[user_root, i1]; X = mean_k embU[q2nb[q,k]] + embQ2[q]
__global__ void k_x1q(const int* __restrict__ user, const int* __restrict__ unb,
                      const int* __restrict__ q2nb,
                      const float* __restrict__ embU, const float* __restrict__ embQ2)
{
    int warp = (blockIdx.x*blockDim.x + threadIdx.x) >> 5;
    int lane = threadIdx.x & 31;
    if (warp >= BT_*NBR_) return;
    int i1 = warp % NBR_, n = warp / NBR_;
    int b = n / (T_-1), t = n % (T_-1);
    int q = unb[user[b*T_+t]*NBR_ + i1];
    int nl = 0;
    if (lane < NBR_) nl = q2nb[q*NBR_+lane];
    int nb[NBR_];
    #pragma unroll
    for (int k = 0; k < NBR_; k++) nb[k] = __shfl_sync(0xffffffffu, nl, k);
    for (int d = lane; d < D_; d += 32) {
        float s = 0.f;
        #pragma unroll
        for (int k = 0; k < NBR_; k++) s += embU[(size_t)nb[k]*D_+d];
        d_X1Q[(size_t)warp*D_+d] = s*(1.f/6.f) + embQ2[(size_t)q*D_+d];
    }
}

// tree1 i=1,j=1: X1Qb[n*6+i1] = mean_k Y2U[q2nb[q,k]] + Y1Q[n*6+i1]
__global__ void k_m1q(const int* __restrict__ user, const int* __restrict__ unb,
                      const int* __restrict__ q2nb)
{
    int warp = (blockIdx.x*blockDim.x + threadIdx.x) >> 5;
    int lane = threadIdx.x & 31;
    if (warp >= BT_*NBR_) return;
    int i1 = warp % NBR_, n = warp / NBR_;
    int b = n / (T_-1), t = n % (T_-1);
    int q = unb[user[b*T_+t]*NBR_ + i1];
    int nl = 0;
    if (lane < NBR_) nl = q2nb[q*NBR_+lane];
    int nb[NBR_];
    #pragma unroll
    for (int k = 0; k < NBR_; k++) nb[k] = __shfl_sync(0xffffffffu, nl, k);
    for (int d = lane; d < D_; d += 32) {
        float s = 0.f;
        #pragma unroll
        for (int k = 0; k < NBR_; k++) s += d_Y2U[(size_t)nb[k]*D_+d];
        d_X1Qb[(size_t)warp*D_+d] = s*(1.f/6.f) + d_Y1Q[(size_t)warp*D_+d];
    }
}

// out[r] = mean_k big[r*6+k] + small[r]   (tree0 i=1,j=1 per skill)
__global__ void k_meanadd(const float* __restrict__ big, const float* __restrict__ small,
                          float* __restrict__ outp, int rows)
{
    int warp = (blockIdx.x*blockDim.x + threadIdx.x) >> 5;
    int lane = threadIdx.x & 31;
    if (warp >= rows) return;
    for (int d = lane; d < D_; d += 32) {
        float s = 0.f;
        #pragma unroll
        for (int k = 0; k < 6; k++) s += big[(size_t)(warp*6+k)*D_+d];
        outp[(size_t)warp*D_+d] = s*(1.f/6.f) + small[(size_t)warp*D_+d];
    }
}

// i=0,j=0 roots: tree0 mean embS[qnb[q]]+embQ[q]; tree1 mean embQ2[unb[u]]+embU[u]
__global__ void k_x0(const int* __restrict__ question, const int* __restrict__ user,
                     const int* __restrict__ qnb, const int* __restrict__ unb,
                     const float* __restrict__ embQ, const float* __restrict__ embS,
                     const float* __restrict__ embU, const float* __restrict__ embQ2)
{
    int warp = (blockIdx.x*blockDim.x + threadIdx.x) >> 5;
    int lane = threadIdx.x & 31;
    if (warp >= 2*BT_) return;
    int n   = warp % BT_;
    int tau = warp / BT_;
    int b = n / (T_-1), t = n % (T_-1);
    int root = (tau == 0) ? question[b*T_+t] : user[b*T_+t];
    int l1l = 0;
    if (lane < NBR_) l1l = (tau == 0) ? qnb[root*NBR_+lane] : unb[root*NBR_+lane];
    int l1[NBR_];
    #pragma unroll
    for (int k = 0; k < NBR_; k++) l1[k] = __shfl_sync(0xffffffffu, l1l, k);
    const float* T1 = (tau == 0) ? embS : embQ2;
    const float* T0 = (tau == 0) ? embQ : embU;
    for (int d = lane; d < D_; d += 32) {
        float s = 0.f;
        #pragma unroll
        for (int k = 0; k < NBR_; k++) s += T1[(size_t)l1[k]*D_+d];
        d_X0[(size_t)warp*D_+d] = s*(1.f/6.f) + T0[(size_t)root*D_+d];
    }
}

// root-level mean of level-1 values: tree0 via YS[qnb[root]], tree1 via YQ[n*6+k]
__global__ void k_rootmean(const int* __restrict__ question, const int* __restrict__ qnb,
                           const float* __restrict__ YS, const float* __restrict__ YQ,
                           const float* __restrict__ small, float* __restrict__ outp)
{
    int warp = (blockIdx.x*blockDim.x + threadIdx.x) >> 5;
    int lane = threadIdx.x & 31;
    if (warp >= 2*BT_) return;
    int n   = warp % BT_;
    int tau = warp / BT_;
    int b = n / (T_-1), t = n % (T_-1);
    int idx[NBR_];
    if (tau == 0) {
        int root = question[b*T_+t];
        int il = 0;
        if (lane < NBR_) il = qnb[root*NBR_+lane];
        #pragma unroll
        for (int k = 0; k < NBR_; k++) idx[k] = __shfl_sync(0xffffffffu, il, k);
    } else {
        #pragma unroll
        for (int k = 0; k < NBR_; k++) idx[k] = n*NBR_+k;
    }
    const float* src = (tau == 0) ? YS : YQ;
    for (int d = lane; d < D_; d += 32) {
        float s = 0.f;
        #pragma unroll
        for (int k = 0; k < NBR_; k++) s += src[(size_t)idx[k]*D_+d];
        outp[(size_t)warp*D_+d] = s*(1.f/6.f) + small[(size_t)warp*D_+d];
    }
}

// ---------------- fusion input ----------------
__global__ void k_fuse(const int* __restrict__ question, const int* __restrict__ response,
                       const int* __restrict__ mask,
                       const float* __restrict__ embQ, const float* __restrict__ embQ2,
                       const float* __restrict__ embR,
                       const float* __restrict__ w1q, const float* __restrict__ w2q)
{
    int i = blockIdx.x*blockDim.x + threadIdx.x;
    if (i >= BT_*D_) return;
    int n = i / D_, d = i % D_;
    int b = n / (T_-1), t = n % (T_-1);
    int m = mask[b*T_+t];
    int q = question[b*T_+t];
    int r = response[b*T_+t];
    float e1 = m ? d_E[(size_t)n*D_+d]       : embQ [(size_t)q*D_+d];
    float e2 = m ? d_E[(size_t)(BT_+n)*D_+d] : embQ2[(size_t)q*D_+d];
    d_Xf[(size_t)n*2*D_+d]    = w1q[0]*e1 + w2q[0]*e2;
    d_Xf[(size_t)n*2*D_+D_+d] = embR[(size_t)r*D_+d];
}

// ---------------- qs_concat rows + query logits ----------------
__global__ void k_qs(const int* __restrict__ question, const int* __restrict__ qsidx,
                     const float* __restrict__ embQ, const float* __restrict__ embS,
                     const float* __restrict__ bw)
{
    int n = blockIdx.x;
    int q = threadIdx.x >> 5, lane = threadIdx.x & 31;
    if (q >= 5) return;
    int b = n / (T_-1), t = n % (T_-1);
    int qn = question[b*T_ + t + 1];
    const float* src = (q == 0) ? (embQ + (size_t)qn*D_)
                                : (embS + (size_t)qsidx[qn*SPQ_ + q - 1]*D_);
    float dot = 0.f;
    for (int d = lane; d < D_; d += 32) {
        float v = src[d];
        d_qsc[(size_t)(n*5+q)*D_+d] = v;
        dot = fmaf(v, d_vec[d], dot);
    }
    #pragma unroll
    for (int off = 16; off; off >>= 1) dot += __shfl_xor_sync(0xffffffffu, dot, off);
    if (lane == 0) d_qlog[n*5+q] = dot + d_vec[200] + bw[0];
}

// ---------------- scores + top-10 (mask-before-select, ties -> lowest index) ----------------
__global__ void k_topk(const int* __restrict__ question, const float* __restrict__ embQ)
{
    __shared__ float qn_s[D_];
    __shared__ float sc[T_];
    int n = blockIdx.x, tid = threadIdx.x;
    int b = n / (T_-1), t = n % (T_-1);
    int qn = question[b*T_ + t + 1];
    for (int d = tid; d < D_; d += 64) qn_s[d] = embQ[(size_t)qn*D_+d];
    __syncthreads();
    if (tid < T_) {
        float s = NEG_;
        if (tid < t) {
            const float* row = embQ + (size_t)question[b*T_+tid]*D_;
            float a0 = 0.f, a1 = 0.f;
            for (int d = 0; d < D_; d += 2) {
                a0 = fmaf(row[d],   qn_s[d],   a0);
                a1 = fmaf(row[d+1], qn_s[d+1], a1);
            }
            s = a0 + a1;
        }
        sc[tid] = s;
    }
    __syncthreads();
    if (tid < 32) {
        float v0 = sc[tid];                               int i0  = tid;
        float v1 = (tid+32 < T_) ? sc[tid+32] : -FLT_MAX; int i1t = tid + 32;
        for (int r = 0; r < 10; r++) {
            float bv; int bi;
            if (v0 > v1 || (v0 == v1 && i0 < i1t)) { bv = v0; bi = i0; } else { bv = v1; bi = i1t; }
            #pragma unroll
            for (int off = 16; off; off >>= 1) {
                float ov = __shfl_xor_sync(0xffffffffu, bv, off);
                int   oi = __shfl_xor_sync(0xffffffffu, bi, off);
                if (ov > bv || (ov == bv && oi < bi)) { bv = ov; bi = oi; }
            }
            if (tid == 0) {
                d_topk[n*10+r]   = bi;
                d_sval[n*11+1+r] = (bi < t) ? 1 : 0;
            }
            if (i0  == bi) v0 = -FLT_MAX;
            if (i1t == bi) v1 = -FLT_MAX;
        }
        if (tid == 0) d_sval[n*11] = 1;
    }
}

// ---------------- sequential LSTM + attention readout ----------------
__global__ void __launch_bounds__(416,1) k_seq(const int* __restrict__ mask,
                                               const float* __restrict__ Whh,
                                               float* __restrict__ out)
{
    __shared__ float sh[T_][D_];
    __shared__ float kh[T_];
    __shared__ float h[D_], c[D_], g[4*D_];
    __shared__ float gm[55], lg[55];
    int b = blockIdx.x, tid = threadIdx.x;
    int lane = tid & 31, warp = tid >> 5;   // 13 warps
    for (int i = tid; i < T_*D_; i += 416) (&sh[0][0])[i] = 0.f;
    for (int i = tid; i < D_; i += 416) { h[i] = 0.f; c[i] = 0.f; }
    if (tid < T_) kh[tid] = 0.f;
    if (tid == 0) out[b*T_] = 0.5f;
    float w[D_];
    if (tid < 4*D_) {
        #pragma unroll
        for (int j = 0; j < D_; j++) w[j] = Whh[(size_t)tid*D_+j];
    }
    __syncthreads();
    for (int t = 0; t < T_-1; t++) {
        int n = b*(T_-1)+t;
        if (tid < 4*D_) {
            float s = d_gip[(size_t)n*4*D_+tid];
            #pragma unroll
            for (int j = 0; j < D_; j++) s = fmaf(w[j], h[j], s);
            g[tid] = s;
        }
        __syncthreads();
        int m = mask[b*T_+t];
        if (tid < D_) {
            float gi = g[tid], gf = g[D_+tid], gg = g[2*D_+tid], go = g[3*D_+tid];
            float c2 = sigf(gf)*c[tid] + sigf(gi)*tanhf(gg);
            float h2 = sigf(go)*tanhf(c2);
            float hn = m ? h2 : h[tid];
            float cn = m ? c2 : c[tid];
            h[tid] = hn; c[tid] = cn; sh[t][tid] = hn;
        }
        __syncthreads();
        if (warp == 0) {
            float s = 0.f;
            for (int d = lane; d < D_; d += 32) s = fmaf(d_vec[D_+d], h[d], s);
            #pragma unroll
            for (int o = 16; o; o >>= 1) s += __shfl_xor_sync(0xffffffffu, s, o);
            if (lane == 0) kh[t] = s;
        }
        __syncthreads();
        for (int p = warp; p < 55; p += 13) {
            int q = p / 11, sidx = p % 11;
            const float* qr = d_qsc + (size_t)(n*5+q)*D_;
            const float* st;
            float kl; int valid;
            if (sidx == 0) { st = h; kl = kh[t]; valid = 1; }
            else {
                int ii = d_topk[n*10 + sidx - 1];
                st = sh[ii]; kl = kh[ii]; valid = d_sval[n*11 + sidx];
            }
            float s = 0.f;
            for (int d = lane; d < D_; d += 32) s = fmaf(qr[d], st[d], s);
            #pragma unroll
            for (int o = 16; o; o >>= 1) s += __shfl_xor_sync(0xffffffffu, s, o);
            if (lane == 0) {
                gm[p] = s;
                lg[p] = valid ? (d_qlog[n*5+q] + kl + d_vec[201]) : NEG_;
            }
        }
        __syncthreads();
        if (warp == 0) {
            float mx = -FLT_MAX;
            for (int p = lane; p < 55; p += 32) mx = fmaxf(mx, lg[p]);
            #pragma unroll
            for (int o = 16; o; o >>= 1) mx = fmaxf(mx, __shfl_xor_sync(0xffffffffu, mx, o));
            float se = 0.f, sg = 0.f;
            for (int p = lane; p < 55; p += 32) {
                float e = expf(lg[p] - mx);
                se += e; sg = fmaf(e, gm[p], sg);
            }
            #pragma unroll
            for (int o = 16; o; o >>= 1) {
                se += __shfl_xor_sync(0xffffffffu, se, o);
                sg += __shfl_xor_sync(0xffffffffu, sg, o);
            }
            if (lane == 0) out[b*T_ + t + 1] = sigf(sg / se);
        }
        __syncthreads();
    }
}

// ---------------- host launcher ----------------
#define SYM(p, s) do { void* v_; cudaGetSymbolAddress(&v_, s); p = (float*)v_; } while (0)
#define WGRID(rows) dim3(((rows)*32 + 255)/256)

extern "C" void kernel_launch(void* const* d_in, const int* in_sizes, int n_in,
                              void* d_out, int out_size)
{
    const int *user=(const int*)d_in[0], *question=(const int*)d_in[1];
    const int *response=(const int*)d_in[2], *mask=(const int*)d_in[3];
    const int *qnb=(const int*)d_in[4], *snb=(const int*)d_in[5];
    const int *unb=(const int*)d_in[6], *q2nb=(const int*)d_in[7], *qsidx=(const int*)d_in[8];
    const float *embQ=(const float*)d_in[9], *embQ2=(const float*)d_in[10];
    const float *embS=(const float*)d_in[11], *embU=(const float*)d_in[12], *embR=(const float*)d_in[13];
    const float *w1q=(const float*)d_in[14], *w2q=(const float*)d_in[15];
    const float *Wih=(const float*)d_in[16], *Whh=(const float*)d_in[17];
    const float *bih=(const float*)d_in[18], *bhh=(const float*)d_in[19];
    const float *aggw=(const float*)d_in[20], *aggb=(const float*)d_in[21];
    const float *Wal=(const float*)d_in[22], *bal=(const float*)d_in[23];
    const float *Wq=(const float*)d_in[24], *bq=(const float*)d_in[25];
    const float *Wk=(const float*)d_in[26], *bk=(const float*)d_in[27];
    const float *Ww=(const float*)d_in[28], *bw=(const float*)d_in[29];
    const float *Wf=(const float*)d_in[30], *bf=(const float*)d_in[31];
    float* out = (float*)d_out;

    float *X2Q, *Y2Q, *X1S, *Y1S, *X1Sb, *Y1Sb, *X2U, *Y2U;
    float *X1Q, *Y1Q, *X1Qb, *Y1Qb;
    float *X0, *Y0, *X0b, *Y0b, *X0c, *Y0c, *E, *Xf, *et, *gip, *bsum;
    SYM(X2Q, d_X2Q); SYM(Y2Q, d_Y2Q); SYM(X1S, d_X1S); SYM(Y1S, d_Y1S);
    SYM(X1Sb, d_X1Sb); SYM(Y1Sb, d_Y1Sb); SYM(X2U, d_X2U); SYM(Y2U, d_Y2U);
    SYM(X1Q, d_X1Q); SYM(Y1Q, d_Y1Q); SYM(X1Qb, d_X1Qb); SYM(Y1Qb, d_Y1Qb);
    SYM(X0, d_X0); SYM(Y0, d_Y0); SYM(X0b, d_X0b); SYM(Y0b, d_Y0b);
    SYM(X0c, d_X0c); SYM(Y0c, d_Y0c); SYM(E, d_E); SYM(Xf, d_Xf);
    SYM(et, d_et); SYM(gip, d_gip); SYM(bsum, d_bsum);

    const float* w2 = aggw + 2*D_*D_;
    const float* w1 = aggw + 1*D_*D_;
    const float* w0 = aggw;
    const float* b2 = aggb + 2*D_;
    const float* b1 = aggb + 1*D_;
    const float* b0 = aggb;

    dim3 tb(256);
    k_vec<<<1, 512>>>(Wq, bq, Wk, bk, Ww, bih, bhh);

    // ---- tree0 per-node levels ----
    k_x2q<<<WGRID(NS_*NBR_), tb>>>(snb, qnb, embQ, embS);
    gemm_k<<<dim3(2, (NS_*NBR_+63)/64), tb>>>(X2Q, w2, b2, Y2Q, NS_*NBR_, D_, D_, 1);
    k_x1s<<<WGRID(NS_), tb>>>(snb, embQ, embS);
    gemm_k<<<dim3(2, (NS_+63)/64), tb>>>(X1S, w1, b1, Y1S, NS_, D_, D_, 1);
    k_meanadd<<<WGRID(NS_), tb>>>(Y2Q, Y1S, X1Sb, NS_);
    gemm_k<<<dim3(2, (NS_+63)/64), tb>>>(X1Sb, w1, b1, Y1Sb, NS_, D_, D_, 1);

    // ---- tree1 per-node levels ----
    k_x2u<<<WGRID(NU_), tb>>>(unb, embQ2, embU);
    gemm_k<<<dim3(2, (NU_+63)/64), tb>>>(X2U, w2, b2, Y2U, NU_, D_, D_, 1);
    k_x1q<<<WGRID(BT_*NBR_), tb>>>(user, unb, q2nb, embU, embQ2);
    gemm_k<<<dim3(2, (BT_*NBR_+63)/64), tb>>>(X1Q, w1, b1, Y1Q, BT_*NBR_, D_, D_, 1);
    k_m1q<<<WGRID(BT_*NBR_), tb>>>(user, unb, q2nb);
    gemm_k<<<dim3(2, (BT_*NBR_+63)/64), tb>>>(X1Qb, w1, b1, Y1Qb, BT_*NBR_, D_, D_, 1);

    // ---- root level (both trees, 2*BT rows) ----
    k_x0<<<WGRID(2*BT_), tb>>>(question, user, qnb, unb, embQ, embS, embU, embQ2);
    gemm_k<<<dim3(2, (2*BT_+63)/64), tb>>>(X0, w0, b0, Y0, 2*BT_, D_, D_, 1);
    k_rootmean<<<WGRID(2*BT_), tb>>>(question, qnb, Y1S, Y1Q, Y0, X0b);
    gemm_k<<<dim3(2, (2*BT_+63)/64), tb>>>(X0b, w0, b0, Y0b, 2*BT_, D_, D_, 1);
    k_rootmean<<<WGRID(2*BT_), tb>>>(question, qnb, Y1Sb, Y1Qb, Y0b, X0c);
    gemm_k<<<dim3(2, (2*BT_+63)/64), tb>>>(X0c, w0, b0, Y0c, 2*BT_, D_, D_, 1);
    gemm_k<<<dim3(2, (2*BT_+63)/64), tb>>>(Y0c, Wal, bal, E, 2*BT_, D_, D_, 1);

    // ---- fusion + gates ----
    k_fuse<<<(BT_*D_ + 255)/256, 256>>>(question, response, mask, embQ, embQ2, embR, w1q, w2q);
    gemm_k<<<dim3(2, (BT_+63)/64), tb>>>(Xf, Wf, bf, et, BT_, D_, 2*D_, 2);
    gemm_k<<<dim3(7, (BT_+63)/64), tb>>>(et, Wih, bsum, gip, BT_, 4*D_, D_, 0);

    // ---- attention inputs ----
    k_qs<<<BT_, 160>>>(question, qsidx, embQ, embS, bw);
    k_topk<<<BT_, 64>>>(question, embQ);

    // ---- sequential recurrence + readout ----
    k_seq<<<B_, 416>>>(mask, Whh, out);
}

// round 17
// speedup vs baseline: 1.3442x; 1.1190x over previous
#include <cuda_runtime.h>
#include <math.h>
#include <float.h>

#define B_   32
#define T_   50
#define D_   100
#define NQ_  20000
#define NS_  500
#define NU_  10000
#define NBR_ 6
#define SPQ_ 4
#define BT_  (B_*(T_-1))
#define NEG_ (-1.0e9f)

// ---------------- static device scratch ----------------
__device__ float d_X2Q[NS_*NBR_*D_];
__device__ float d_Y2Q[NS_*NBR_*D_];
__device__ float d_X1S[NS_*D_];
__device__ float d_Y1S[NS_*D_];
__device__ float d_X1Sb[NS_*D_];
__device__ float d_Y1Sb[NS_*D_];
__device__ float d_X2U[NU_*D_];
__device__ float d_Y2U[NU_*D_];
__device__ float d_X1Q[BT_*NBR_*D_];
__device__ float d_Y1Q[BT_*NBR_*D_];
__device__ float d_X1Qb[BT_*NBR_*D_];
__device__ float d_Y1Qb[BT_*NBR_*D_];
__device__ float d_X0 [2*BT_*D_];
__device__ float d_Y0 [2*BT_*D_];
__device__ float d_X0b[2*BT_*D_];
__device__ float d_Y0b[2*BT_*D_];
__device__ float d_X0c[2*BT_*D_];
__device__ float d_E  [2*BT_*D_];
__device__ float d_gip[BT_*4*D_];
__device__ float d_qsc[BT_*5*D_];
__device__ float d_qlog[BT_*5];
__device__ int   d_topk[BT_*10];
__device__ int   d_sval[BT_*11];
__device__ float d_vec[256];      // [0:100) qvec, [100:200) kvec, [200] cq, [201] ck
__device__ float d_bsum[4*D_];
__device__ float d_rproj[2*D_];   // emb_response[r] @ W_fusion[:,D:]^T

__device__ __forceinline__ float sigf(float x){ return 1.f/(1.f+expf(-x)); }

// ================= batched GEMM: per-segment C = tanh(A@W^T + b), N=K=100 =================
struct GSeg { const float* A; float* C; const float* W; const float* bias; int M; int tstart; };
struct GDesc { GSeg s[5]; int nseg; };

__global__ void gemm_batch(GDesc gd)
{
    __shared__ float As[16][65];
    __shared__ float Bs[16][65];
    int mt = blockIdx.x;
    int si = 0;
    #pragma unroll
    for (int i = 1; i < 5; i++) if (i < gd.nseg && mt >= gd.s[i].tstart) si = i;
    const GSeg sg = gd.s[si];
    const int bm = (mt - sg.tstart) * 64, bn = blockIdx.y * 64;
    const int M = sg.M;
    const int tid = threadIdx.x;
    const int tr = tid >> 4, tc = tid & 15;
    float acc[4][4] = {};
    for (int k0 = 0; k0 < D_; k0 += 16) {
        for (int i = tid; i < 1024; i += 256) {
            int m = i >> 4, k = i & 15;
            int gm = bm + m, gk = k0 + k;
            As[k][m] = (gm < M && gk < D_) ? sg.A[(size_t)gm * D_ + gk] : 0.f;
        }
        for (int i = tid; i < 1024; i += 256) {
            int nn = i >> 4, k = i & 15;
            int gn = bn + nn, gk = k0 + k;
            Bs[k][nn] = (gn < D_ && gk < D_) ? sg.W[(size_t)gn * D_ + gk] : 0.f;
        }
        __syncthreads();
        #pragma unroll
        for (int k = 0; k < 16; k++) {
            float a[4], b[4];
            #pragma unroll
            for (int i = 0; i < 4; i++) a[i] = As[k][tr*4+i];
            #pragma unroll
            for (int j = 0; j < 4; j++) b[j] = Bs[k][tc*4+j];
            #pragma unroll
            for (int i = 0; i < 4; i++)
                #pragma unroll
                for (int j = 0; j < 4; j++) acc[i][j] = fmaf(a[i], b[j], acc[i][j]);
        }
        __syncthreads();
    }
    #pragma unroll
    for (int i = 0; i < 4; i++) {
        int gm = bm + tr*4 + i;
        if (gm >= M) continue;
        #pragma unroll
        for (int j = 0; j < 4; j++) {
            int gn = bn + tc*4 + j;
            if (gn >= D_) continue;
            sg.C[(size_t)gm * D_ + gn] = tanhf(acc[i][j] + sg.bias[gn]);
        }
    }
}

// ================= prep: attention vectors, combined bias, response projection =================
__global__ void k_prep(const float* __restrict__ Wq, const float* __restrict__ bq,
                       const float* __restrict__ Wk, const float* __restrict__ bk,
                       const float* __restrict__ Ww,
                       const float* __restrict__ bih, const float* __restrict__ bhh,
                       const float* __restrict__ embR, const float* __restrict__ Wf)
{
    int tid = threadIdx.x;
    if (tid < D_) {
        float s = 0.f;
        for (int j = 0; j < D_; j++) s = fmaf(Ww[j], Wq[j*D_+tid], s);
        d_vec[tid] = s;
    } else if (tid < 2*D_) {
        int d = tid - D_;
        float s = 0.f;
        for (int j = 0; j < D_; j++) s = fmaf(Ww[D_+j], Wk[j*D_+d], s);
        d_vec[D_+d] = s;
    } else if (tid == 2*D_) {
        float s = 0.f; for (int j = 0; j < D_; j++) s = fmaf(bq[j], Ww[j], s);
        d_vec[200] = s;
    } else if (tid == 2*D_+1) {
        float s = 0.f; for (int j = 0; j < D_; j++) s = fmaf(bk[j], Ww[D_+j], s);
        d_vec[201] = s;
    }
    if (tid < 4*D_) d_bsum[tid] = bih[tid] + bhh[tid];
    if (tid < 2*D_) {
        int r = tid / D_, n = tid % D_;
        float s = 0.f;
        for (int k = 0; k < D_; k++) s = fmaf(embR[r*D_+k], Wf[n*2*D_ + D_ + k], s);
        d_rproj[tid] = s;
    }
}

// ================= fused depth-0 gathers (warp-segment dispatch) =================
#define G0_X2Q 0
#define G0_X1S 3000
#define G0_X2U 3500
#define G0_X1Q 13500
#define G0_X0  22908
#define G0_END 26044

__global__ void k_gather0(const int* __restrict__ question, const int* __restrict__ user,
                          const int* __restrict__ qnb, const int* __restrict__ snb,
                          const int* __restrict__ unb, const int* __restrict__ q2nb,
                          const float* __restrict__ embQ, const float* __restrict__ embS,
                          const float* __restrict__ embU, const float* __restrict__ embQ2)
{
    int gwarp = (blockIdx.x*blockDim.x + threadIdx.x) >> 5;
    int lane = threadIdx.x & 31;
    if (gwarp >= G0_END) return;
    const float *Tn, *Ts_;   // neighbor table (mean), self table
    float* outp;
    int self, nbl = 0;
    if (gwarp < G0_X1S) {                       // x2q
        int w = gwarp;
        int q = snb[w];
        if (lane < NBR_) nbl = qnb[q*NBR_+lane];
        Tn = embS; Ts_ = embQ; self = q; outp = d_X2Q + (size_t)w*D_;
    } else if (gwarp < G0_X2U) {                // x1s
        int w = gwarp - G0_X1S;
        if (lane < NBR_) nbl = snb[w*NBR_+lane];
        Tn = embQ; Ts_ = embS; self = w; outp = d_X1S + (size_t)w*D_;
    } else if (gwarp < G0_X1Q) {                // x2u
        int w = gwarp - G0_X2U;
        if (lane < NBR_) nbl = unb[w*NBR_+lane];
        Tn = embQ2; Ts_ = embU; self = w; outp = d_X2U + (size_t)w*D_;
    } else if (gwarp < G0_X0) {                 // x1q
        int w = gwarp - G0_X1Q;
        int i1 = w % NBR_, n = w / NBR_;
        int b = n / (T_-1), t = n % (T_-1);
        int q = unb[user[b*T_+t]*NBR_ + i1];
        if (lane < NBR_) nbl = q2nb[q*NBR_+lane];
        Tn = embU; Ts_ = embQ2; self = q; outp = d_X1Q + (size_t)w*D_;
    } else {                                    // x0 (both trees)
        int w = gwarp - G0_X0;
        int n = w % BT_, tau = w / BT_;
        int b = n / (T_-1), t = n % (T_-1);
        int root = (tau == 0) ? question[b*T_+t] : user[b*T_+t];
        if (lane < NBR_) nbl = (tau == 0) ? qnb[root*NBR_+lane] : unb[root*NBR_+lane];
        Tn = (tau == 0) ? embS : embQ2;
        Ts_ = (tau == 0) ? embQ : embU;
        self = root; outp = d_X0 + (size_t)w*D_;
    }
    int nb[NBR_];
    #pragma unroll
    for (int k = 0; k < NBR_; k++) nb[k] = __shfl_sync(0xffffffffu, nbl, k);
    for (int d = lane; d < D_; d += 32) {
        float s = 0.f;
        #pragma unroll
        for (int k = 0; k < NBR_; k++) s += Tn[(size_t)nb[k]*D_+d];
        outp[d] = s*(1.f/6.f) + Ts_[(size_t)self*D_+d];
    }
}

// ================= fused depth-2 gathers =================
#define G2_MS  0
#define G2_M1Q 500
#define G2_RM  9908
#define G2_END 13044

__global__ void k_gather2(const int* __restrict__ question, const int* __restrict__ user,
                          const int* __restrict__ qnb, const int* __restrict__ unb,
                          const int* __restrict__ q2nb)
{
    int gwarp = (blockIdx.x*blockDim.x + threadIdx.x) >> 5;
    int lane = threadIdx.x & 31;
    if (gwarp >= G2_END) return;
    if (gwarp < G2_M1Q) {                       // X1Sb[s] = mean Y2Q[s*6+k] + Y1S[s]
        int w = gwarp;
        for (int d = lane; d < D_; d += 32) {
            float s = 0.f;
            #pragma unroll
            for (int k = 0; k < NBR_; k++) s += d_Y2Q[(size_t)(w*NBR_+k)*D_+d];
            d_X1Sb[(size_t)w*D_+d] = s*(1.f/6.f) + d_Y1S[(size_t)w*D_+d];
        }
    } else if (gwarp < G2_RM) {                 // X1Qb
        int w = gwarp - G2_M1Q;
        int i1 = w % NBR_, n = w / NBR_;
        int b = n / (T_-1), t = n % (T_-1);
        int q = unb[user[b*T_+t]*NBR_ + i1];
        int nbl = 0;
        if (lane < NBR_) nbl = q2nb[q*NBR_+lane];
        int nb[NBR_];
        #pragma unroll
        for (int k = 0; k < NBR_; k++) nb[k] = __shfl_sync(0xffffffffu, nbl, k);
        for (int d = lane; d < D_; d += 32) {
            float s = 0.f;
            #pragma unroll
            for (int k = 0; k < NBR_; k++) s += d_Y2U[(size_t)nb[k]*D_+d];
            d_X1Qb[(size_t)w*D_+d] = s*(1.f/6.f) + d_Y1Q[(size_t)w*D_+d];
        }
    } else {                                    // X0b rootmean over Y1S / Y1Q + Y0
        int w = gwarp - G2_RM;
        int n = w % BT_, tau = w / BT_;
        int b = n / (T_-1), t = n % (T_-1);
        int idx[NBR_];
        if (tau == 0) {
            int root = question[b*T_+t];
            int il = 0;
            if (lane < NBR_) il = qnb[root*NBR_+lane];
            #pragma unroll
            for (int k = 0; k < NBR_; k++) idx[k] = __shfl_sync(0xffffffffu, il, k);
        } else {
            #pragma unroll
            for (int k = 0; k < NBR_; k++) idx[k] = n*NBR_+k;
        }
        const float* src = (tau == 0) ? d_Y1S : d_Y1Q;
        for (int d = lane; d < D_; d += 32) {
            float s = 0.f;
            #pragma unroll
            for (int k = 0; k < NBR_; k++) s += src[(size_t)idx[k]*D_+d];
            d_X0b[(size_t)w*D_+d] = s*(1.f/6.f) + d_Y0[(size_t)w*D_+d];
        }
    }
}

// ================= X0c rootmean (depth 4) =================
__global__ void k_x0c(const int* __restrict__ question, const int* __restrict__ qnb)
{
    int gwarp = (blockIdx.x*blockDim.x + threadIdx.x) >> 5;
    int lane = threadIdx.x & 31;
    if (gwarp >= 2*BT_) return;
    int n = gwarp % BT_, tau = gwarp / BT_;
    int b = n / (T_-1), t = n % (T_-1);
    int idx[NBR_];
    if (tau == 0) {
        int root = question[b*T_+t];
        int il = 0;
        if (lane < NBR_) il = qnb[root*NBR_+lane];
        #pragma unroll
        for (int k = 0; k < NBR_; k++) idx[k] = __shfl_sync(0xffffffffu, il, k);
    } else {
        #pragma unroll
        for (int k = 0; k < NBR_; k++) idx[k] = n*NBR_+k;
    }
    const float* src = (tau == 0) ? d_Y1Sb : d_Y1Qb;
    for (int d = lane; d < D_; d += 32) {
        float s = 0.f;
        #pragma unroll
        for (int k = 0; k < NBR_; k++) s += src[(size_t)idx[k]*D_+d];
        d_X0c[(size_t)gwarp*D_+d] = s*(1.f/6.f) + d_Y0b[(size_t)gwarp*D_+d];
    }
}

// ================= fused 2-stage GEMM: E = tanh(tanh(X0c@w0^T+b0)@Wal^T+bal) =================
__global__ void k_gemm2(const float* __restrict__ w0, const float* __restrict__ b0,
                        const float* __restrict__ Wal, const float* __restrict__ bal)
{
    __shared__ float As[16][65];
    __shared__ float Bs[16][104];
    __shared__ float Ts[64][101];
    const int bm = blockIdx.x * 64;
    const int M = 2*BT_;
    const int tid = threadIdx.x;
    const int tr = tid >> 4, tc = tid & 15;
    float acc[2][4][4] = {};
    // ---- stage 1: T = tanh(X0c @ w0^T + b0) ----
    for (int k0 = 0; k0 < D_; k0 += 16) {
        for (int i = tid; i < 1024; i += 256) {
            int m = i >> 4, k = i & 15;
            int gm = bm + m, gk = k0 + k;
            As[k][m] = (gm < M && gk < D_) ? d_X0c[(size_t)gm * D_ + gk] : 0.f;
        }
        for (int i = tid; i < 1600; i += 256) {
            int k = i / 100, n = i % 100;
            int gk = k0 + k;
            Bs[k][n] = (gk < D_) ? w0[(size_t)n * D_ + gk] : 0.f;
        }
        __syncthreads();
        #pragma unroll
        for (int k = 0; k < 16; k++) {
            float a[4];
            #pragma unroll
            for (int i = 0; i < 4; i++) a[i] = As[k][tr*4+i];
            #pragma unroll
            for (int nt = 0; nt < 2; nt++) {
                #pragma unroll
                for (int j = 0; j < 4; j++) {
                    int col = nt*64 + tc*4 + j;
                    float bv = (col < 100) ? Bs[k][col] : 0.f;
                    #pragma unroll
                    for (int i = 0; i < 4; i++) acc[nt][i][j] = fmaf(a[i], bv, acc[nt][i][j]);
                }
            }
        }
        __syncthreads();
    }
    #pragma unroll
    for (int nt = 0; nt < 2; nt++)
        #pragma unroll
        for (int i = 0; i < 4; i++)
            #pragma unroll
            for (int j = 0; j < 4; j++) {
                int col = nt*64 + tc*4 + j;
                if (col < 100) Ts[tr*4+i][col] = tanhf(acc[nt][i][j] + b0[col]);
            }
    __syncthreads();
    // ---- stage 2: E = tanh(T @ Wal^T + bal) ----
    #pragma unroll
    for (int nt = 0; nt < 2; nt++)
        #pragma unroll
        for (int i = 0; i < 4; i++)
            #pragma unroll
            for (int j = 0; j < 4; j++) acc[nt][i][j] = 0.f;
    for (int k0 = 0; k0 < D_; k0 += 16) {
        for (int i = tid; i < 1600; i += 256) {
            int k = i / 100, n = i % 100;
            int gk = k0 + k;
            Bs[k][n] = (gk < D_) ? Wal[(size_t)n * D_ + gk] : 0.f;
        }
        __syncthreads();
        int kk = (k0 + 16 <= D_) ? 16 : (D_ - k0);
        for (int k = 0; k < kk; k++) {
            float a[4];
            #pragma unroll
            for (int i = 0; i < 4; i++) a[i] = Ts[tr*4+i][k0+k];
            #pragma unroll
            for (int nt = 0; nt < 2; nt++) {
                #pragma unroll
                for (int j = 0; j < 4; j++) {
                    int col = nt*64 + tc*4 + j;
                    float bv = (col < 100) ? Bs[k][col] : 0.f;
                    #pragma unroll
                    for (int i = 0; i < 4; i++) acc[nt][i][j] = fmaf(a[i], bv, acc[nt][i][j]);
                }
            }
        }
        __syncthreads();
    }
    #pragma unroll
    for (int nt = 0; nt < 2; nt++)
        #pragma unroll
        for (int i = 0; i < 4; i++) {
            int gm = bm + tr*4 + i;
            if (gm >= M) continue;
            #pragma unroll
            for (int j = 0; j < 4; j++) {
                int col = nt*64 + tc*4 + j;
                if (col < 100) d_E[(size_t)gm * D_ + col] = tanhf(acc[nt][i][j] + bal[col]);
            }
        }
}

// ================= fused tail: ehat -> et=relu(.) -> gip = et@Wih^T + bsum =================
__global__ void k_tail(const int* __restrict__ question, const int* __restrict__ response,
                       const int* __restrict__ mask,
                       const float* __restrict__ embQ, const float* __restrict__ embQ2,
                       const float* __restrict__ w1q, const float* __restrict__ w2q,
                       const float* __restrict__ Wf, const float* __restrict__ bf,
                       const float* __restrict__ Wih)
{
    __shared__ float Xh[64][101];
    __shared__ float Bs[16][104];
    __shared__ int   rr[64];
    const int bm = blockIdx.x * 64;
    const int tid = threadIdx.x;
    const int tr = tid >> 4, tc = tid & 15;
    const float w1 = w1q[0], w2 = w2q[0];
    // ---- stage 0: build ehat rows + response ids ----
    for (int idx = tid; idx < 64*D_; idx += 256) {
        int row = idx / D_, d = idx % D_;
        int n = bm + row;
        float v = 0.f;
        if (n < BT_) {
            int b = n / (T_-1), t = n % (T_-1);
            int m = mask[b*T_+t];
            int q = question[b*T_+t];
            float e1 = m ? d_E[(size_t)n*D_+d]       : embQ [(size_t)q*D_+d];
            float e2 = m ? d_E[(size_t)(BT_+n)*D_+d] : embQ2[(size_t)q*D_+d];
            v = w1*e1 + w2*e2;
            if (d == 0) rr[row] = response[b*T_+t];
        } else if (d == 0) rr[row] = 0;
        Xh[row][d] = v;
    }
    __syncthreads();
    // ---- stage 1: et = relu(ehat @ Wf[:,:D]^T + rproj[r] + bf), kept in registers ----
    float acc[2][4][4] = {};
    for (int k0 = 0; k0 < D_; k0 += 16) {
        for (int i = tid; i < 1600; i += 256) {
            int k = i / 100, n = i % 100;
            int gk = k0 + k;
            Bs[k][n] = (gk < D_) ? Wf[(size_t)n * 2*D_ + gk] : 0.f;
        }
        __syncthreads();
        int kk = (k0 + 16 <= D_) ? 16 : (D_ - k0);
        for (int k = 0; k < kk; k++) {
            float a[4];
            #pragma unroll
            for (int i = 0; i < 4; i++) a[i] = Xh[tr*4+i][k0+k];
            #pragma unroll
            for (int nt = 0; nt < 2; nt++) {
                #pragma unroll
                for (int j = 0; j < 4; j++) {
                    int col = nt*64 + tc*4 + j;
                    float bv = (col < 100) ? Bs[k][col] : 0.f;
                    #pragma unroll
                    for (int i = 0; i < 4; i++) acc[nt][i][j] = fmaf(a[i], bv, acc[nt][i][j]);
                }
            }
        }
        __syncthreads();
    }
    // write et into Xh (overwrite; fully consumed above)
    #pragma unroll
    for (int nt = 0; nt < 2; nt++)
        #pragma unroll
        for (int i = 0; i < 4; i++) {
            int row = tr*4+i;
            #pragma unroll
            for (int j = 0; j < 4; j++) {
                int col = nt*64 + tc*4 + j;
                if (col < 100) {
                    float v = acc[nt][i][j] + bf[col] + d_rproj[rr[row]*D_ + col];
                    Xh[row][col] = fmaxf(v, 0.f);
                }
            }
        }
    __syncthreads();
    // ---- stage 2: gip = et @ Wih^T + bsum, N=400 ----
    for (int nt = 0; nt < 7; nt++) {
        int bn = nt * 64;
        float a2[4][4] = {};
        for (int k0 = 0; k0 < D_; k0 += 16) {
            for (int i = tid; i < 1024; i += 256) {
                int nn = i >> 4, k = i & 15;
                int gn = bn + nn, gk = k0 + k;
                Bs[k][nn] = (gn < 4*D_ && gk < D_) ? Wih[(size_t)gn * D_ + gk] : 0.f;
            }
            __syncthreads();
            int kk = (k0 + 16 <= D_) ? 16 : (D_ - k0);
            for (int k = 0; k < kk; k++) {
                float a[4], b[4];
                #pragma unroll
                for (int i = 0; i < 4; i++) a[i] = Xh[tr*4+i][k0+k];
                #pragma unroll
                for (int j = 0; j < 4; j++) b[j] = Bs[k][tc*4+j];
                #pragma unroll
                for (int i = 0; i < 4; i++)
                    #pragma unroll
                    for (int j = 0; j < 4; j++) a2[i][j] = fmaf(a[i], b[j], a2[i][j]);
            }
            __syncthreads();
        }
        #pragma unroll
        for (int i = 0; i < 4; i++) {
            int gm = bm + tr*4 + i;
            if (gm >= BT_) continue;
            #pragma unroll
            for (int j = 0; j < 4; j++) {
                int gn = bn + tc*4 + j;
                if (gn < 4*D_) d_gip[(size_t)gm * 4*D_ + gn] = a2[i][j] + d_bsum[gn];
            }
        }
    }
}

// ================= qs rows + logits + top-10 (merged) =================
__global__ void k_qstop(const int* __restrict__ question, const int* __restrict__ qsidx,
                        const float* __restrict__ embQ, const float* __restrict__ embS,
                        const float* __restrict__ bw)
{
    __shared__ float qn_s[D_];
    __shared__ float sc[T_];
    int n = blockIdx.x, tid = threadIdx.x;
    int q = tid >> 5, lane = tid & 31;
    int b = n / (T_-1), t = n % (T_-1);
    int qn = question[b*T_ + t + 1];
    for (int d = tid; d < D_; d += 160) qn_s[d] = embQ[(size_t)qn*D_+d];
    __syncthreads();
    // ---- qs part (5 warps) ----
    {
        const float* src = (q == 0) ? (embQ + (size_t)qn*D_)
                                    : (embS + (size_t)qsidx[qn*SPQ_ + q - 1]*D_);
        float dot = 0.f;
        for (int d = lane; d < D_; d += 32) {
            float v = src[d];
            d_qsc[(size_t)(n*5+q)*D_+d] = v;
            dot = fmaf(v, d_vec[d], dot);
        }
        #pragma unroll
        for (int off = 16; off; off >>= 1) dot += __shfl_xor_sync(0xffffffffu, dot, off);
        if (lane == 0) d_qlog[n*5+q] = dot + d_vec[200] + bw[0];
    }
    // ---- scores ----
    if (tid < T_) {
        float s = NEG_;
        if (tid < t) {
            const float* row = embQ + (size_t)question[b*T_+tid]*D_;
            float a0 = 0.f, a1 = 0.f;
            for (int d = 0; d < D_; d += 2) {
                a0 = fmaf(row[d],   qn_s[d],   a0);
                a1 = fmaf(row[d+1], qn_s[d+1], a1);
            }
            s = a0 + a1;
        }
        sc[tid] = s;
    }
    __syncthreads();
    // ---- top-10 selection (warp 0) ----
    if (tid < 32) {
        float v0 = sc[tid];                               int i0  = tid;
        float v1 = (tid+32 < T_) ? sc[tid+32] : -FLT_MAX; int i1t = tid + 32;
        for (int r = 0; r < 10; r++) {
            float bv; int bi;
            if (v0 > v1 || (v0 == v1 && i0 < i1t)) { bv = v0; bi = i0; } else { bv = v1; bi = i1t; }
            #pragma unroll
            for (int off = 16; off; off >>= 1) {
                float ov = __shfl_xor_sync(0xffffffffu, bv, off);
                int   oi = __shfl_xor_sync(0xffffffffu, bi, off);
                if (ov > bv || (ov == bv && oi < bi)) { bv = ov; bi = oi; }
            }
            if (tid == 0) {
                d_topk[n*10+r]   = bi;
                d_sval[n*11+1+r] = (bi < t) ? 1 : 0;
            }
            if (i0  == bi) v0 = -FLT_MAX;
            if (i1t == bi) v1 = -FLT_MAX;
        }
        if (tid == 0) d_sval[n*11] = 1;
    }
}

// ================= sequential LSTM + attention readout =================
__global__ void __launch_bounds__(416,1) k_seq(const int* __restrict__ mask,
                                               const float* __restrict__ Whh,
                                               float* __restrict__ out)
{
    __shared__ float sh[T_][D_];
    __shared__ float kh[T_];
    __shared__ float h[D_], c[D_], g[4*D_];
    __shared__ float gm[55], lg[55];
    int b = blockIdx.x, tid = threadIdx.x;
    int lane = tid & 31, warp = tid >> 5;
    for (int i = tid; i < T_*D_; i += 416) (&sh[0][0])[i] = 0.f;
    for (int i = tid; i < D_; i += 416) { h[i] = 0.f; c[i] = 0.f; }
    if (tid < T_) kh[tid] = 0.f;
    if (tid == 0) out[b*T_] = 0.5f;
    float w[D_];
    if (tid < 4*D_) {
        #pragma unroll
        for (int j = 0; j < D_; j++) w[j] = Whh[(size_t)tid*D_+j];
    }
    __syncthreads();
    for (int t = 0; t < T_-1; t++) {
        int n = b*(T_-1)+t;
        if (tid < 4*D_) {
            float s = d_gip[(size_t)n*4*D_+tid];
            #pragma unroll
            for (int j = 0; j < D_; j++) s = fmaf(w[j], h[j], s);
            g[tid] = s;
        }
        __syncthreads();
        int m = mask[b*T_+t];
        if (tid < D_) {
            float gi = g[tid], gf = g[D_+tid], gg = g[2*D_+tid], go = g[3*D_+tid];
            float c2 = sigf(gf)*c[tid] + sigf(gi)*tanhf(gg);
            float h2 = sigf(go)*tanhf(c2);
            float hn = m ? h2 : h[tid];
            float cn = m ? c2 : c[tid];
            h[tid] = hn; c[tid] = cn; sh[t][tid] = hn;
        }
        __syncthreads();
        if (warp == 0) {
            float s = 0.f;
            for (int d = lane; d < D_; d += 32) s = fmaf(d_vec[D_+d], h[d], s);
            #pragma unroll
            for (int o = 16; o; o >>= 1) s += __shfl_xor_sync(0xffffffffu, s, o);
            if (lane == 0) kh[t] = s;
        }
        __syncthreads();
        for (int p = warp; p < 55; p += 13) {
            int q = p / 11, sidx = p % 11;
            const float* qr = d_qsc + (size_t)(n*5+q)*D_;
            const float* st;
            float kl; int valid;
            if (sidx == 0) { st = h; kl = kh[t]; valid = 1; }
            else {
                int ii = d_topk[n*10 + sidx - 1];
                st = sh[ii]; kl = kh[ii]; valid = d_sval[n*11 + sidx];
            }
            float s = 0.f;
            for (int d = lane; d < D_; d += 32) s = fmaf(qr[d], st[d], s);
            #pragma unroll
            for (int o = 16; o; o >>= 1) s += __shfl_xor_sync(0xffffffffu, s, o);
            if (lane == 0) {
                gm[p] = s;
                lg[p] = valid ? (d_qlog[n*5+q] + kl + d_vec[201]) : NEG_;
            }
        }
        __syncthreads();
        if (warp == 0) {
            float mx = -FLT_MAX;
            for (int p = lane; p < 55; p += 32) mx = fmaxf(mx, lg[p]);
            #pragma unroll
            for (int o = 16; o; o >>= 1) mx = fmaxf(mx, __shfl_xor_sync(0xffffffffu, mx, o));
            float se = 0.f, sg = 0.f;
            for (int p = lane; p < 55; p += 32) {
                float e = expf(lg[p] - mx);
                se += e; sg = fmaf(e, gm[p], sg);
            }
            #pragma unroll
            for (int o = 16; o; o >>= 1) {
                se += __shfl_xor_sync(0xffffffffu, se, o);
                sg += __shfl_xor_sync(0xffffffffu, sg, o);
            }
            if (lane == 0) out[b*T_ + t + 1] = sigf(sg / se);
        }
        __syncthreads();
    }
}

// ---------------- host launcher ----------------
#define SYM(p, s) do { void* v_; cudaGetSymbolAddress(&v_, s); p = (float*)v_; } while (0)

extern "C" void kernel_launch(void* const* d_in, const int* in_sizes, int n_in,
                              void* d_out, int out_size)
{
    const int *user=(const int*)d_in[0], *question=(const int*)d_in[1];
    const int *response=(const int*)d_in[2], *mask=(const int*)d_in[3];
    const int *qnb=(const int*)d_in[4], *snb=(const int*)d_in[5];
    const int *unb=(const int*)d_in[6], *q2nb=(const int*)d_in[7], *qsidx=(const int*)d_in[8];
    const float *embQ=(const float*)d_in[9], *embQ2=(const float*)d_in[10];
    const float *embS=(const float*)d_in[11], *embU=(const float*)d_in[12], *embR=(const float*)d_in[13];
    const float *w1q=(const float*)d_in[14], *w2q=(const float*)d_in[15];
    const float *Wih=(const float*)d_in[16], *Whh=(const float*)d_in[17];
    const float *bih=(const float*)d_in[18], *bhh=(const float*)d_in[19];
    const float *aggw=(const float*)d_in[20], *aggb=(const float*)d_in[21];
    const float *Wal=(const float*)d_in[22], *bal=(const float*)d_in[23];
    const float *Wq=(const float*)d_in[24], *bq=(const float*)d_in[25];
    const float *Wk=(const float*)d_in[26], *bk=(const float*)d_in[27];
    const float *Ww=(const float*)d_in[28], *bw=(const float*)d_in[29];
    const float *Wf=(const float*)d_in[30], *bf=(const float*)d_in[31];
    float* out = (float*)d_out;

    float *X2Q, *Y2Q, *X1S, *Y1S, *X1Sb, *Y1Sb, *X2U, *Y2U;
    float *X1Q, *Y1Q, *X1Qb, *Y1Qb, *X0, *Y0, *X0b, *Y0b;
    SYM(X2Q, d_X2Q); SYM(Y2Q, d_Y2Q); SYM(X1S, d_X1S); SYM(Y1S, d_Y1S);
    SYM(X1Sb, d_X1Sb); SYM(Y1Sb, d_Y1Sb); SYM(X2U, d_X2U); SYM(Y2U, d_Y2U);
    SYM(X1Q, d_X1Q); SYM(Y1Q, d_Y1Q); SYM(X1Qb, d_X1Qb); SYM(Y1Qb, d_Y1Qb);
    SYM(X0, d_X0); SYM(Y0, d_Y0); SYM(X0b, d_X0b); SYM(Y0b, d_Y0b);

    const float* w2 = aggw + 2*D_*D_;
    const float* w1 = aggw + 1*D_*D_;
    const float* w0 = aggw;
    const float* b2 = aggb + 2*D_;
    const float* b1 = aggb + 1*D_;
    const float* b0 = aggb;

    // 1. prep
    k_prep<<<1, 512>>>(Wq, bq, Wk, bk, Ww, bih, bhh, embR, Wf);
    // 2. depth-0 gathers (26044 warps)
    k_gather0<<<(G0_END*32 + 255)/256, 256>>>(question, user, qnb, snb, unb, q2nb,
                                              embQ, embS, embU, embQ2);
    // 3. qs rows + logits + topk (needs d_vec)
    k_qstop<<<BT_, 160>>>(question, qsidx, embQ, embS, bw);
    // 4. depth-1 batched GEMM (5 segments; tiles 47,8,157,147,49 -> 408)
    {
        GDesc gd;
        gd.s[0] = { X2Q, Y2Q, w2, b2, NS_*NBR_,  0   };
        gd.s[1] = { X1S, Y1S, w1, b1, NS_,       47  };
        gd.s[2] = { X2U, Y2U, w2, b2, NU_,       55  };
        gd.s[3] = { X1Q, Y1Q, w1, b1, BT_*NBR_,  212 };
        gd.s[4] = { X0,  Y0,  w0, b0, 2*BT_,     359 };
        gd.nseg = 5;
        gemm_batch<<<dim3(408, 2), 256>>>(gd);
    }
    // 5. depth-2 gathers (13044 warps)
    k_gather2<<<(G2_END*32 + 255)/256, 256>>>(question, user, qnb, unb, q2nb);
    // 6. depth-3 batched GEMM (3 segments; tiles 8,147,49 -> 204)
    {
        GDesc gd;
        gd.s[0] = { X1Sb, Y1Sb, w1, b1, NS_,      0   };
        gd.s[1] = { X1Qb, Y1Qb, w1, b1, BT_*NBR_, 8   };
        gd.s[2] = { X0b,  Y0b,  w0, b0, 2*BT_,    155 };
        gd.s[3] = gd.s[2]; gd.s[4] = gd.s[2];
        gd.nseg = 3;
        gemm_batch<<<dim3(204, 2), 256>>>(gd);
    }
    // 7. X0c rootmean
    k_x0c<<<(2*BT_*32 + 255)/256, 256>>>(question, qnb);
    // 8. Y0c -> E fused 2-stage GEMM
    k_gemm2<<<(2*BT_ + 63)/64, 256>>>(w0, b0, Wal, bal);
    // 9. fused tail: ehat -> et -> gip
    k_tail<<<(BT_ + 63)/64, 256>>>(question, response, mask, embQ, embQ2,
                                   w1q, w2q, Wf, bf, Wih);
    // 10. sequential recurrence + readout
    k_seq<<<B_, 416>>>(mask, Whh, out);
}